// round 5
// baseline (speedup 1.0000x reference)
#include <cuda_runtime.h>
#include <cstdint>

#define N_NODES 100000
#define N_EDGES 3200000
#define F_IN    128
#define F_HID   16
#define F_OUT   20

// ---------------- scratch (static device globals; no allocation) ----------------
__device__ int   g_is32;                        // 1 if edge_index is int32
__device__ __align__(16) int2  g_edge[N_EDGES]; // packed (src,dst)
__device__ __align__(16) float g_deg [N_NODES];
__device__ __align__(16) float g_dinv[N_NODES];
__device__ __align__(16) float g_y1  [N_NODES * F_HID];
__device__ __align__(16) float g_acc1[N_NODES * F_HID];
__device__ __align__(16) float g_y2  [N_NODES * F_HID];   // layer-2 agg in 16-dim (W2 deferred)
__device__ __align__(16) float g_acc2[N_NODES * F_HID];

// ---------------- vector atomic add (sm_90+ family) ----------------
__device__ __forceinline__ void red_add_v4(float* p, float4 v) {
    asm volatile("red.global.add.v4.f32 [%0], {%1, %2, %3, %4};"
                 :: "l"(p), "f"(v.x), "f"(v.y), "f"(v.z), "f"(v.w)
                 : "memory");
}

// ---------------- kernels ----------------

// Detect index dtype from first 64 int64 words (int32 data reinterpreted puts a
// neighbor index in the high bits -> out of range). Deterministic.
__global__ void k_detect(const long long* __restrict__ ei64) {
    if (threadIdx.x == 0 && blockIdx.x == 0) {
        int is32 = 0;
        for (int i = 0; i < 64; i++) {
            long long v = ei64[i];
            if (v < 0 || v >= (long long)N_NODES) { is32 = 1; break; }
        }
        g_is32 = is32;
    }
}

__global__ void k_init_deg() {
    int i = blockIdx.x * blockDim.x + threadIdx.x;
    if (i < N_NODES) g_deg[i] = 1.0f;   // self-loop
}

// Pack edges into int2 scratch + accumulate degree at dst.
__global__ void __launch_bounds__(256) k_convert(const void* __restrict__ ei) {
    int e = blockIdx.x * blockDim.x + threadIdx.x;
    if (e >= N_EDGES) return;
    int s, d;
    if (g_is32) {
        const int* p = (const int*)ei;
        s = __ldcs(&p[e]);
        d = __ldcs(&p[N_EDGES + e]);
    } else {
        const long long* p = (const long long*)ei;
        s = (int)__ldcs(&p[e]);
        d = (int)__ldcs(&p[N_EDGES + e]);
    }
    g_edge[e] = make_int2(s, d);
    atomicAdd(&g_deg[d], 1.0f);
}

// Warp-per-node coalesced GEMM1: y1 = dinv * (x @ W1); acc1 = y1 (self-loop).
// Lane i loads float4 #i of the 128-float row -> one contiguous 512B per warp.
__global__ void __launch_bounds__(256) k_gemm1(const float* __restrict__ x,
                                               const float* __restrict__ W1) {
    __shared__ float Ws[F_IN * F_HID];      // 8 KB
    for (int i = threadIdx.x; i < F_IN * F_HID; i += blockDim.x) Ws[i] = W1[i];
    __syncthreads();

    int warp = (blockIdx.x * blockDim.x + threadIdx.x) >> 5;
    int lane = threadIdx.x & 31;
    if (warp >= N_NODES) return;

    float4 v = __ldcs((const float4*)(x + (size_t)warp * F_IN) + lane);

    float acc[F_HID];
    const float* w = &Ws[(4 * lane) * F_HID];
#pragma unroll
    for (int j = 0; j < F_HID; j++) {
        acc[j] = v.x * w[j]
               + v.y * w[F_HID + j]
               + v.z * w[2 * F_HID + j]
               + v.w * w[3 * F_HID + j];
    }
    // butterfly reduce across 32 lanes
#pragma unroll
    for (int off = 16; off >= 1; off >>= 1) {
#pragma unroll
        for (int j = 0; j < F_HID; j++)
            acc[j] += __shfl_xor_sync(0xFFFFFFFFu, acc[j], off);
    }

    float dinv = rsqrtf(g_deg[warp]);
    if (lane == 0) g_dinv[warp] = dinv;

    if (lane < 4) {
        float4 t;
        t.x = acc[4 * lane + 0] * dinv;
        t.y = acc[4 * lane + 1] * dinv;
        t.z = acc[4 * lane + 2] * dinv;
        t.w = acc[4 * lane + 3] * dinv;
        ((float4*)&g_y1  [(size_t)warp * F_HID])[lane] = t;
        ((float4*)&g_acc1[(size_t)warp * F_HID])[lane] = t;
    }
}

// acc[dst] += y[src]   (16 floats per edge, 4x red.v4)
// LAYER selects the global buffer pair IN DEVICE CODE (no device-symbol args).
template <int LAYER>
__global__ void __launch_bounds__(256) k_scatter() {
    const float* __restrict__ y   = (LAYER == 1) ? g_y1   : g_y2;
    float*       __restrict__ acc = (LAYER == 1) ? g_acc1 : g_acc2;
    int e = blockIdx.x * blockDim.x + threadIdx.x;
    if (e >= N_EDGES) return;
    int2 ed = __ldcs(&g_edge[e]);       // evict-first: keep y/acc resident in L2
    const float4* ys = (const float4*)(y + (size_t)ed.x * F_HID);
    float*        ot = acc + (size_t)ed.y * F_HID;
#pragma unroll
    for (int j = 0; j < F_HID / 4; j++) red_add_v4(ot + 4 * j, ys[j]);
}

// h = relu(dinv*acc1 + b1) ; y2 = dinv*h (16-dim; W2 deferred) ; acc2 = y2
__global__ void __launch_bounds__(128) k_layer2_prep(const float* __restrict__ b1) {
    __shared__ float bs[F_HID];
    if (threadIdx.x < F_HID) bs[threadIdx.x] = b1[threadIdx.x];
    __syncthreads();

    int n = blockIdx.x * blockDim.x + threadIdx.x;
    if (n >= N_NODES) return;

    float dinv = g_dinv[n];
    const float4* a1 = (const float4*)&g_acc1[(size_t)n * F_HID];
    float4* y = (float4*)&g_y2[(size_t)n * F_HID];
    float4* a = (float4*)&g_acc2[(size_t)n * F_HID];
#pragma unroll
    for (int j = 0; j < F_HID / 4; j++) {
        float4 v = a1[j];
        float4 t;
        t.x = fmaxf(v.x * dinv + bs[4 * j + 0], 0.0f) * dinv;
        t.y = fmaxf(v.y * dinv + bs[4 * j + 1], 0.0f) * dinv;
        t.z = fmaxf(v.z * dinv + bs[4 * j + 2], 0.0f) * dinv;
        t.w = fmaxf(v.w * dinv + bs[4 * j + 3], 0.0f) * dinv;
        y[j] = t;
        a[j] = t;
    }
}

// logits = (dinv*acc2) @ W2 + b2 ; out = log_softmax(logits)
__global__ void __launch_bounds__(128) k_finalize(const float* __restrict__ W2,
                                                  const float* __restrict__ b2,
                                                  float* __restrict__ out) {
    __shared__ float Ws[F_HID * F_OUT];
    __shared__ float bs[F_OUT];
    for (int i = threadIdx.x; i < F_HID * F_OUT; i += blockDim.x) Ws[i] = W2[i];
    if (threadIdx.x < F_OUT) bs[threadIdx.x] = b2[threadIdx.x];
    __syncthreads();

    int n = blockIdx.x * blockDim.x + threadIdx.x;
    if (n >= N_NODES) return;

    float dinv = g_dinv[n];
    float h[F_HID];
    const float4* a2 = (const float4*)&g_acc2[(size_t)n * F_HID];
#pragma unroll
    for (int j = 0; j < F_HID / 4; j++) {
        float4 v = a2[j];
        h[4 * j + 0] = v.x * dinv;
        h[4 * j + 1] = v.y * dinv;
        h[4 * j + 2] = v.z * dinv;
        h[4 * j + 3] = v.w * dinv;
    }

    float l[F_OUT];
#pragma unroll
    for (int j = 0; j < F_OUT; j++) l[j] = bs[j];
#pragma unroll
    for (int k = 0; k < F_HID; k++) {
        float hk = h[k];
        const float* w = &Ws[k * F_OUT];
#pragma unroll
        for (int j = 0; j < F_OUT; j++) l[j] += hk * w[j];
    }

    float m = l[0];
#pragma unroll
    for (int j = 1; j < F_OUT; j++) m = fmaxf(m, l[j]);
    float s = 0.0f;
#pragma unroll
    for (int j = 0; j < F_OUT; j++) s += expf(l[j] - m);
    float lse = m + logf(s);

    float4* o = (float4*)(out + (size_t)n * F_OUT);
#pragma unroll
    for (int j = 0; j < F_OUT / 4; j++) {
        float4 t;
        t.x = l[4 * j + 0] - lse;
        t.y = l[4 * j + 1] - lse;
        t.z = l[4 * j + 2] - lse;
        t.w = l[4 * j + 3] - lse;
        o[j] = t;
    }
}

// ---------------- launch ----------------
extern "C" void kernel_launch(void* const* d_in, const int* in_sizes, int n_in,
                              void* d_out, int out_size) {
    // Bind inputs BY ELEMENT COUNT:
    //   x:12,800,000  edge_index:6,400,000  W1:2048  b1:16  W2:320  b2:20
    const float* x  = nullptr;
    const void*  ei = nullptr;
    const float* W1 = nullptr;
    const float* b1 = nullptr;
    const float* W2 = nullptr;
    const float* b2 = nullptr;

    for (int i = 0; i < n_in; i++) {
        switch (in_sizes[i]) {
            case 12800000: x  = (const float*)d_in[i]; break;
            case  6400000: ei = d_in[i];               break;
            case     2048: W1 = (const float*)d_in[i]; break;
            case       16: b1 = (const float*)d_in[i]; break;
            case      320: W2 = (const float*)d_in[i]; break;
            case       20: b2 = (const float*)d_in[i]; break;
            default: break;
        }
    }
    if (!x || !ei || !W1 || !b1 || !W2 || !b2) return;

    float* out = (float*)d_out;

    const int nodeBlocks128 = (N_NODES + 127) / 128;
    const int nodeBlocks256 = (N_NODES + 255) / 256;
    const int edgeBlocks256 = (N_EDGES + 255) / 256;
    const int gemmBlocks    = (N_NODES * 32 + 255) / 256;   // warp per node

    k_detect     <<<1, 32>>>((const long long*)ei);
    k_init_deg   <<<nodeBlocks256, 256>>>();
    k_convert    <<<edgeBlocks256, 256>>>(ei);
    k_gemm1      <<<gemmBlocks, 256>>>(x, W1);
    k_scatter<1> <<<edgeBlocks256, 256>>>();
    k_layer2_prep<<<nodeBlocks128, 128>>>(b1);
    k_scatter<2> <<<edgeBlocks256, 256>>>();
    k_finalize   <<<nodeBlocks128, 128>>>(W2, b2, out);
}

// round 6
// speedup vs baseline: 2.7425x; 2.7425x over previous
#include <cuda_runtime.h>
#include <cstdint>

#define N_NODES 100000
#define N_EDGES 3200000
#define F_IN    128
#define F_HID   16
#define F_OUT   20

#define SCAN_B  512
#define SCAN_NB ((N_NODES + SCAN_B - 1) / SCAN_B)   // 196

// ---------------- scratch (static device globals; no allocation) ----------------
__device__ int g_is32;                            // 1 if edge_index is int32
__device__ __align__(16) int   g_degi  [N_NODES]; // in-degree (no self loop)
__device__ __align__(16) int   g_off   [N_NODES]; // CSR exclusive offsets
__device__ __align__(16) int   g_cursor[N_NODES]; // fill cursors
__device__ __align__(16) int   g_part  [SCAN_NB];
__device__ __align__(16) int   g_part2 [SCAN_NB];
__device__ __align__(16) int   g_csr   [N_EDGES]; // src ids grouped by dst
__device__ __align__(16) float g_dinv[N_NODES];
__device__ __align__(16) float g_y1  [N_NODES * F_HID];
__device__ __align__(16) float g_acc1[N_NODES * F_HID];
__device__ __align__(16) float g_y2  [N_NODES * F_HID];   // layer-2 agg in 16-dim (W2 deferred)
__device__ __align__(16) float g_acc2[N_NODES * F_HID];

// ---------------- kernels ----------------

// Detect index dtype from first 64 int64 words (int32 data reinterpreted puts a
// neighbor index in the high bits -> out of range). Deterministic.
__global__ void k_detect(const long long* __restrict__ ei64) {
    if (threadIdx.x == 0 && blockIdx.x == 0) {
        int is32 = 0;
        for (int i = 0; i < 64; i++) {
            long long v = ei64[i];
            if (v < 0 || v >= (long long)N_NODES) { is32 = 1; break; }
        }
        g_is32 = is32;
    }
}

__global__ void k_zero_deg() {
    int i = blockIdx.x * blockDim.x + threadIdx.x;
    if (i < N_NODES) g_degi[i] = 0;
}

// In-degree histogram from dst column only.
__global__ void __launch_bounds__(256) k_degree(const void* __restrict__ ei) {
    int e = blockIdx.x * blockDim.x + threadIdx.x;
    if (e >= N_EDGES) return;
    int d;
    if (g_is32) d = __ldcs(&((const int*)ei)[N_EDGES + e]);
    else        d = (int)__ldcs(&((const long long*)ei)[N_EDGES + e]);
    atomicAdd(&g_degi[d], 1);
}

// ---- 3-kernel exclusive scan over g_degi -> g_off (and cursors) ----
__global__ void __launch_bounds__(SCAN_B) k_scanA() {
    __shared__ int sh[SCAN_B];
    int i = blockIdx.x * SCAN_B + threadIdx.x;
    int v = (i < N_NODES) ? g_degi[i] : 0;
    sh[threadIdx.x] = v;
    __syncthreads();
#pragma unroll
    for (int off = 1; off < SCAN_B; off <<= 1) {
        int t = (threadIdx.x >= off) ? sh[threadIdx.x - off] : 0;
        __syncthreads();
        if (threadIdx.x >= off) sh[threadIdx.x] += t;
        __syncthreads();
    }
    int incl = sh[threadIdx.x];
    if (i < N_NODES) g_off[i] = incl - v;      // block-local exclusive
    if (threadIdx.x == SCAN_B - 1) g_part[blockIdx.x] = incl;
}

__global__ void __launch_bounds__(256) k_scanB() {
    __shared__ int sh[256];
    int v = (threadIdx.x < SCAN_NB) ? g_part[threadIdx.x] : 0;
    sh[threadIdx.x] = v;
    __syncthreads();
#pragma unroll
    for (int off = 1; off < 256; off <<= 1) {
        int t = (threadIdx.x >= off) ? sh[threadIdx.x - off] : 0;
        __syncthreads();
        if (threadIdx.x >= off) sh[threadIdx.x] += t;
        __syncthreads();
    }
    if (threadIdx.x < SCAN_NB) g_part2[threadIdx.x] = sh[threadIdx.x] - v;  // exclusive
}

__global__ void __launch_bounds__(SCAN_B) k_scanC() {
    int i = blockIdx.x * SCAN_B + threadIdx.x;
    if (i < N_NODES) {
        int o = g_off[i] + g_part2[blockIdx.x];
        g_off[i] = o;
        g_cursor[i] = o;
    }
}

// Scatter edges into CSR slots (grouped by dst, order within group arbitrary).
__global__ void __launch_bounds__(256) k_fill(const void* __restrict__ ei) {
    int e = blockIdx.x * blockDim.x + threadIdx.x;
    if (e >= N_EDGES) return;
    int s, d;
    if (g_is32) {
        const int* p = (const int*)ei;
        s = __ldcs(&p[e]);
        d = __ldcs(&p[N_EDGES + e]);
    } else {
        const long long* p = (const long long*)ei;
        s = (int)__ldcs(&p[e]);
        d = (int)__ldcs(&p[N_EDGES + e]);
    }
    int slot = atomicAdd(&g_cursor[d], 1);
    g_csr[slot] = s;
}

// Tiled GEMM1: 256 nodes/block, K chunked by 32 via smem (stride-33: conflict-free).
// y1 = dinv * (x @ W1); also writes dinv.
__global__ void __launch_bounds__(256) k_gemm1(const float* __restrict__ x,
                                               const float* __restrict__ W1) {
    __shared__ float Ws[F_IN * F_HID];   // 8 KB
    __shared__ float xs[256 * 33];       // 33 KB, stride 33 words
    for (int i = threadIdx.x; i < F_IN * F_HID; i += blockDim.x) Ws[i] = W1[i];

    int t = threadIdx.x;
    int base = blockIdx.x * 256;

    float acc[F_HID];
#pragma unroll
    for (int j = 0; j < F_HID; j++) acc[j] = 0.0f;

    for (int kc = 0; kc < F_IN; kc += 32) {
        __syncthreads();
        // coalesced load: warp covers 4 rows x 128B contiguous
#pragma unroll
        for (int it = 0; it < 8; it++) {
            int f  = it * 256 + t;        // 0..2047
            int r  = f >> 3;
            int c4 = f & 7;
            int nn = min(base + r, N_NODES - 1);
            float4 v = __ldcs((const float4*)(x + (size_t)nn * F_IN + kc) + c4);
            float* dp = &xs[r * 33 + c4 * 4];
            dp[0] = v.x; dp[1] = v.y; dp[2] = v.z; dp[3] = v.w;
        }
        __syncthreads();
#pragma unroll
        for (int k = 0; k < 32; k++) {
            float xv = xs[t * 33 + k];                      // bank (t+k)%32: conflict-free
            const float4* wr = (const float4*)&Ws[(kc + k) * F_HID];  // broadcast
            float4 w0 = wr[0], w1 = wr[1], w2 = wr[2], w3 = wr[3];
            acc[0]  += xv * w0.x;  acc[1]  += xv * w0.y;
            acc[2]  += xv * w0.z;  acc[3]  += xv * w0.w;
            acc[4]  += xv * w1.x;  acc[5]  += xv * w1.y;
            acc[6]  += xv * w1.z;  acc[7]  += xv * w1.w;
            acc[8]  += xv * w2.x;  acc[9]  += xv * w2.y;
            acc[10] += xv * w2.z;  acc[11] += xv * w2.w;
            acc[12] += xv * w3.x;  acc[13] += xv * w3.y;
            acc[14] += xv * w3.z;  acc[15] += xv * w3.w;
        }
    }

    int n = base + t;
    if (n >= N_NODES) return;
    float dinv = rsqrtf((float)(g_degi[n] + 1));   // +1 self-loop
    g_dinv[n] = dinv;
    float4* y = (float4*)&g_y1[(size_t)n * F_HID];
#pragma unroll
    for (int j = 0; j < F_HID / 4; j++) {
        float4 v;
        v.x = acc[4 * j + 0] * dinv;
        v.y = acc[4 * j + 1] * dinv;
        v.z = acc[4 * j + 2] * dinv;
        v.w = acc[4 * j + 3] * dinv;
        y[j] = v;
    }
}

// Pure-read aggregation: warp per node, 4 lanes per edge (one float4 each),
// 8 edges per iteration, shuffle-reduce, single non-atomic store.
// acc[n] = y[n] + sum_{s in in(n)} y[s]
template <int LAYER>
__global__ void __launch_bounds__(256) k_agg() {
    const float* __restrict__ y   = (LAYER == 1) ? g_y1   : g_y2;
    float*       __restrict__ acc = (LAYER == 1) ? g_acc1 : g_acc2;

    int n = (blockIdx.x * blockDim.x + threadIdx.x) >> 5;
    if (n >= N_NODES) return;
    int lane = threadIdx.x & 31;
    int sub  = lane >> 2;     // edge slot within group of 8
    int c4   = lane & 3;      // float4 component

    int beg = g_off[n];
    int deg = g_degi[n];

    float4 a = make_float4(0.f, 0.f, 0.f, 0.f);
    for (int i = sub; i < deg; i += 8) {
        int src = __ldg(&g_csr[beg + i]);                       // 4-lane broadcast
        float4 v = ((const float4*)(y + (size_t)src * F_HID))[c4];
        a.x += v.x; a.y += v.y; a.z += v.z; a.w += v.w;
    }
    // reduce the 8 edge-slots (lanes xor 4, 8, 16)
#pragma unroll
    for (int off = 4; off <= 16; off <<= 1) {
        a.x += __shfl_xor_sync(0xFFFFFFFFu, a.x, off);
        a.y += __shfl_xor_sync(0xFFFFFFFFu, a.y, off);
        a.z += __shfl_xor_sync(0xFFFFFFFFu, a.z, off);
        a.w += __shfl_xor_sync(0xFFFFFFFFu, a.w, off);
    }
    if (lane < 4) {
        float4 self = ((const float4*)(y + (size_t)n * F_HID))[lane];
        float4 o;
        o.x = a.x + self.x; o.y = a.y + self.y;
        o.z = a.z + self.z; o.w = a.w + self.w;
        ((float4*)(acc + (size_t)n * F_HID))[lane] = o;
    }
}

// h = relu(dinv*acc1 + b1) ; y2 = dinv*h (16-dim; W2 deferred)
__global__ void __launch_bounds__(256) k_layer2_prep(const float* __restrict__ b1) {
    __shared__ float bs[F_HID];
    if (threadIdx.x < F_HID) bs[threadIdx.x] = b1[threadIdx.x];
    __syncthreads();

    int n = blockIdx.x * blockDim.x + threadIdx.x;
    if (n >= N_NODES) return;

    float dinv = g_dinv[n];
    const float4* a1 = (const float4*)&g_acc1[(size_t)n * F_HID];
    float4* y = (float4*)&g_y2[(size_t)n * F_HID];
#pragma unroll
    for (int j = 0; j < F_HID / 4; j++) {
        float4 v = a1[j];
        float4 t;
        t.x = fmaxf(v.x * dinv + bs[4 * j + 0], 0.0f) * dinv;
        t.y = fmaxf(v.y * dinv + bs[4 * j + 1], 0.0f) * dinv;
        t.z = fmaxf(v.z * dinv + bs[4 * j + 2], 0.0f) * dinv;
        t.w = fmaxf(v.w * dinv + bs[4 * j + 3], 0.0f) * dinv;
        y[j] = t;
    }
}

// logits = (dinv*acc2) @ W2 + b2 ; out = log_softmax(logits)
__global__ void __launch_bounds__(128) k_finalize(const float* __restrict__ W2,
                                                  const float* __restrict__ b2,
                                                  float* __restrict__ out) {
    __shared__ float Ws[F_HID * F_OUT];
    __shared__ float bs[F_OUT];
    for (int i = threadIdx.x; i < F_HID * F_OUT; i += blockDim.x) Ws[i] = W2[i];
    if (threadIdx.x < F_OUT) bs[threadIdx.x] = b2[threadIdx.x];
    __syncthreads();

    int n = blockIdx.x * blockDim.x + threadIdx.x;
    if (n >= N_NODES) return;

    float dinv = g_dinv[n];
    float h[F_HID];
    const float4* a2 = (const float4*)&g_acc2[(size_t)n * F_HID];
#pragma unroll
    for (int j = 0; j < F_HID / 4; j++) {
        float4 v = a2[j];
        h[4 * j + 0] = v.x * dinv;
        h[4 * j + 1] = v.y * dinv;
        h[4 * j + 2] = v.z * dinv;
        h[4 * j + 3] = v.w * dinv;
    }

    float l[F_OUT];
#pragma unroll
    for (int j = 0; j < F_OUT; j++) l[j] = bs[j];
#pragma unroll
    for (int k = 0; k < F_HID; k++) {
        float hk = h[k];
        const float* w = &Ws[k * F_OUT];
#pragma unroll
        for (int j = 0; j < F_OUT; j++) l[j] += hk * w[j];
    }

    float m = l[0];
#pragma unroll
    for (int j = 1; j < F_OUT; j++) m = fmaxf(m, l[j]);
    float s = 0.0f;
#pragma unroll
    for (int j = 0; j < F_OUT; j++) s += expf(l[j] - m);
    float lse = m + logf(s);

    float4* o = (float4*)(out + (size_t)n * F_OUT);
#pragma unroll
    for (int j = 0; j < F_OUT / 4; j++) {
        float4 t;
        t.x = l[4 * j + 0] - lse;
        t.y = l[4 * j + 1] - lse;
        t.z = l[4 * j + 2] - lse;
        t.w = l[4 * j + 3] - lse;
        o[j] = t;
    }
}

// ---------------- launch ----------------
extern "C" void kernel_launch(void* const* d_in, const int* in_sizes, int n_in,
                              void* d_out, int out_size) {
    // Bind inputs BY ELEMENT COUNT:
    //   x:12,800,000  edge_index:6,400,000  W1:2048  b1:16  W2:320  b2:20
    const float* x  = nullptr;
    const void*  ei = nullptr;
    const float* W1 = nullptr;
    const float* b1 = nullptr;
    const float* W2 = nullptr;
    const float* b2 = nullptr;

    for (int i = 0; i < n_in; i++) {
        switch (in_sizes[i]) {
            case 12800000: x  = (const float*)d_in[i]; break;
            case  6400000: ei = d_in[i];               break;
            case     2048: W1 = (const float*)d_in[i]; break;
            case       16: b1 = (const float*)d_in[i]; break;
            case      320: W2 = (const float*)d_in[i]; break;
            case       20: b2 = (const float*)d_in[i]; break;
            default: break;
        }
    }
    if (!x || !ei || !W1 || !b1 || !W2 || !b2) return;

    float* out = (float*)d_out;

    const int nodeBlocks256 = (N_NODES + 255) / 256;
    const int edgeBlocks256 = (N_EDGES + 255) / 256;
    const int aggBlocks     = (N_NODES * 32 + 255) / 256;   // warp per node
    const int gemmBlocks    = (N_NODES + 255) / 256;        // 256 nodes per block

    k_detect     <<<1, 32>>>((const long long*)ei);
    k_zero_deg   <<<nodeBlocks256, 256>>>();
    k_degree     <<<edgeBlocks256, 256>>>(ei);
    k_scanA      <<<SCAN_NB, SCAN_B>>>();
    k_scanB      <<<1, 256>>>();
    k_scanC      <<<SCAN_NB, SCAN_B>>>();
    k_fill       <<<edgeBlocks256, 256>>>(ei);
    k_gemm1      <<<gemmBlocks, 256>>>(x, W1);
    k_agg<1>     <<<aggBlocks, 256>>>();
    k_layer2_prep<<<nodeBlocks256, 256>>>(b1);
    k_agg<2>     <<<aggBlocks, 256>>>();
    k_finalize   <<<(N_NODES + 127) / 128, 128>>>(W2, b2, out);
}